// round 8
// baseline (speedup 1.0000x reference)
#include <cuda_runtime.h>
#include <cuda_bf16.h>

// Rcell stochastic filter. out[b,t] = c*dt*x_t, x_{t+1} = M_t x_t + u_t dy_t.
// cov is batch-independent and exactly scalar (p_t*I), so M_t = a_t I + dt*k*J
// acts as complex multiplication m_t = alpha_t - i*dt*k on z = x0 + i*x1.
// With g_t = prod_{j<t} m_j:
//   out[b,t] = gs_t * S_t,  S_t = sum_{s<t} h_s * w[b,s]   (complex)
//   gs_t = c*dt*g_t,  h_s = u_s * conj(g_{s+1}) / |g_{s+1}|^2
// Riccati chain (u_t, alpha_t) is coeffs-independent -> compile-time.
// R8: lane-local serial prefix over 4 consecutive pairs (8 steps), ONE warp
// shfl-scan per 128-pair chunk (4x fewer shfl cascades than R6), 4 rows/warp,
// 2 blocks/SM, 256-block single wave. Tables in smem with +i>>3 padding
// (bank-conflict-free for the lane*4-strided LDS.128 pattern).

#define T_STEPS 2048
#define NPAIR   1024          // T/2: one float4 per 2 steps
#define WARPS_PER_BLOCK 8
#define ROWS_PER_WARP   4
#define LPAIR   4             // consecutive pairs per lane
#define CHUNK   (32 * LPAIR)  // 128 pairs per warp chunk
#define NCHUNK  (NPAIR / CHUNK)  // 8
#define TABSZ   (NPAIR + NPAIR / 8)   // padded table size (1152)

// physical constants (f32, matching reference)
#define AAc (-0.15f)                     // -0.5*gamma
#define DDc (1.25f)                      // gamma*(nbar+0.5)+Lambda
#define CCc (1.2649110640673518f)        // sqrt(4*eta*Lambda)
#define DTc (1e-3f)

__device__ __forceinline__ int pad(int i) { return i + (i >> 3); }

// ---------------------------------------------------------------------------
// Compile-time Riccati chain: u_t = c*p_t + D, alpha_t = 1 + dt*(a - c*u_t)
// ---------------------------------------------------------------------------
struct PTab { float u[T_STEPS]; float al[T_STEPS]; };

constexpr PTab make_ptab() {
    PTab t{};
    float p = 0.0f;
    for (int i = 0; i < T_STEPS; i++) {
        float uu = CCc * p + DDc;
        t.u[i]  = uu;
        t.al[i] = 1.0f + DTc * (AAc - CCc * uu);
        float dcov = 2.0f * AAc * p + DDc - uu * uu;
        p = p + DTc * dcov;
    }
    return t;
}

__device__ PTab d_ptab = make_ptab();

// ---------------------------------------------------------------------------
__global__ void __launch_bounds__(32 * WARPS_PER_BLOCK, 2)
fused_kernel(const float4* __restrict__ dy4, float4* __restrict__ out4,
             const float* __restrict__ coeffs, int B)
{
    __shared__ float4 tabH[TABSZ];   // padded: entry pad(q) = (h_t0, h_t1)
    __shared__ float4 tabG[TABSZ];   // padded: entry pad(q) = (gs_t0, gs_t1)
    __shared__ float  wAggR[WARPS_PER_BLOCK], wAggI[WARPS_PER_BLOCK];

    const int tid  = threadIdx.x;
    const int lane = tid & 31;
    const int warp = tid >> 5;

    // ---- phase 1: build tables (all 256 threads, 8 steps each) ----
    {
        const float beta = DTc * coeffs[0];     // m_t = alpha_t - i*beta

        float pr = 1.0f, pi = 0.0f;
#pragma unroll
        for (int j = 0; j < 8; j++) {
            float al = d_ptab.al[8 * tid + j];
            float nr = fmaf(al, pr,  beta * pi);
            float ni = fmaf(al, pi, -beta * pr);
            pr = nr; pi = ni;
        }

        // warp inclusive scan (complex product)
        float sr = pr, si = pi;
#pragma unroll
        for (int o = 1; o < 32; o <<= 1) {
            float tr = __shfl_up_sync(0xFFFFFFFFu, sr, o);
            float ti = __shfl_up_sync(0xFFFFFFFFu, si, o);
            if (lane >= o) {
                float nr = tr * sr - ti * si;
                float ni = tr * si + ti * sr;
                sr = nr; si = ni;
            }
        }
        if (lane == 31) { wAggR[warp] = sr; wAggI[warp] = si; }

        float er = __shfl_up_sync(0xFFFFFFFFu, sr, 1);
        float ei = __shfl_up_sync(0xFFFFFFFFu, si, 1);
        if (lane == 0) { er = 1.0f; ei = 0.0f; }
        __syncthreads();

#pragma unroll
        for (int w = 0; w < WARPS_PER_BLOCK; w++) {
            if (w < warp) {
                float ar = wAggR[w], ai = wAggI[w];
                float nr = er * ar - ei * ai;
                float ni = er * ai + ei * ar;
                er = nr; ei = ni;
            }
        }

        // er,ei = g at step 8*tid; emit 8 entries (4 padded float4 pairs)
        float gr = er, gi = ei;
        const float K = CCc * DTc;
        float4 H4, G4;
#pragma unroll
        for (int j = 0; j < 8; j++) {
            int t = 8 * tid + j;
            float al = d_ptab.al[t], u = d_ptab.u[t];
            float gsre = K * gr, gsim = K * gi;          // gs_t = c*dt*g_t
            float g1r = fmaf(al, gr,  beta * gi);        // g_{t+1} = m_t*g_t
            float g1i = fmaf(al, gi, -beta * gr);
            float inv = u / fmaf(g1r, g1r, g1i * g1i);
            float hr =  inv * g1r;                       // h_t
            float hi = -inv * g1i;
            if ((j & 1) == 0) {
                H4.x = hr; H4.y = hi; G4.x = gsre; G4.y = gsim;
            } else {
                H4.z = hr; H4.w = hi; G4.z = gsre; G4.w = gsim;
                tabH[pad(t >> 1)] = H4;
                tabG[pad(t >> 1)] = G4;
            }
            gr = g1r; gi = g1i;
        }
        __syncthreads();
    }

    // ---- phase 2: 4 rows/warp, lane-local prefix over 4 pairs/chunk ----
    const int b0 = (blockIdx.x * WARPS_PER_BLOCK + warp) * ROWS_PER_WARP;

    size_t roff[ROWS_PER_WARP];
#pragma unroll
    for (int r = 0; r < ROWS_PER_WARP; r++)
        roff[r] = (size_t)(b0 + r) * NPAIR;

    float accR[ROWS_PER_WARP], accI[ROWS_PER_WARP];
#pragma unroll
    for (int r = 0; r < ROWS_PER_WARP; r++) { accR[r] = 0.f; accI[r] = 0.f; }

#pragma unroll 1
    for (int c = 0; c < NCHUNK; c++) {
        const int qb = c * CHUNK + LPAIR * lane;   // this lane's first pair

        // h table for this lane's 4 pairs (row-independent)
        float4 h0 = tabH[pad(qb + 0)];
        float4 h1 = tabH[pad(qb + 1)];
        float4 h2 = tabH[pad(qb + 2)];
        float4 h3 = tabH[pad(qb + 3)];

        // lane-local inclusive complex prefix P[r][k], k=0..7 steps
        float PR[ROWS_PER_WARP][8], PI[ROWS_PER_WARP][8];
#pragma unroll
        for (int r = 0; r < ROWS_PER_WARP; r++) {
            float4 w0 = __ldg(dy4 + roff[r] + qb + 0);
            float4 w1 = __ldg(dy4 + roff[r] + qb + 1);
            float4 w2 = __ldg(dy4 + roff[r] + qb + 2);
            float4 w3 = __ldg(dy4 + roff[r] + qb + 3);

            float pr, pi;
            pr = h0.x * w0.x - h0.y * w0.y;            // v0
            pi = h0.x * w0.y + h0.y * w0.x;
            PR[r][0] = pr; PI[r][0] = pi;
            pr += h0.z * w0.z - h0.w * w0.w;           // +v1
            pi += h0.z * w0.w + h0.w * w0.z;
            PR[r][1] = pr; PI[r][1] = pi;
            pr += h1.x * w1.x - h1.y * w1.y;
            pi += h1.x * w1.y + h1.y * w1.x;
            PR[r][2] = pr; PI[r][2] = pi;
            pr += h1.z * w1.z - h1.w * w1.w;
            pi += h1.z * w1.w + h1.w * w1.z;
            PR[r][3] = pr; PI[r][3] = pi;
            pr += h2.x * w2.x - h2.y * w2.y;
            pi += h2.x * w2.y + h2.y * w2.x;
            PR[r][4] = pr; PI[r][4] = pi;
            pr += h2.z * w2.z - h2.w * w2.w;
            pi += h2.z * w2.w + h2.w * w2.z;
            PR[r][5] = pr; PI[r][5] = pi;
            pr += h3.x * w3.x - h3.y * w3.y;
            pi += h3.x * w3.y + h3.y * w3.x;
            PR[r][6] = pr; PI[r][6] = pi;
            pr += h3.z * w3.z - h3.w * w3.w;
            pi += h3.z * w3.w + h3.w * w3.z;
            PR[r][7] = pr; PI[r][7] = pi;              // lane total
        }

        // ONE warp scan per chunk over lane totals (4 rows interleaved)
        float sr[ROWS_PER_WARP], si[ROWS_PER_WARP];
#pragma unroll
        for (int r = 0; r < ROWS_PER_WARP; r++) { sr[r] = PR[r][7]; si[r] = PI[r][7]; }
#pragma unroll
        for (int o = 1; o < 32; o <<= 1) {
            float tr[ROWS_PER_WARP], ti[ROWS_PER_WARP];
#pragma unroll
            for (int r = 0; r < ROWS_PER_WARP; r++) {
                tr[r] = __shfl_up_sync(0xFFFFFFFFu, sr[r], o);
                ti[r] = __shfl_up_sync(0xFFFFFFFFu, si[r], o);
            }
            if (lane >= o) {
#pragma unroll
                for (int r = 0; r < ROWS_PER_WARP; r++) {
                    sr[r] += tr[r]; si[r] += ti[r];
                }
            }
        }

        // g table for this lane's 4 pairs (h regs dead now)
        float4 g0 = tabG[pad(qb + 0)];
        float4 g1 = tabG[pad(qb + 1)];
        float4 g2 = tabG[pad(qb + 2)];
        float4 g3 = tabG[pad(qb + 3)];

#pragma unroll
        for (int r = 0; r < ROWS_PER_WARP; r++) {
            // exclusive offset for this lane's first step
            float offR = accR[r] + (sr[r] - PR[r][7]);
            float offI = accI[r] + (si[r] - PI[r][7]);
            accR[r] += __shfl_sync(0xFFFFFFFFu, sr[r], 31);
            accI[r] += __shfl_sync(0xFFFFFFFFu, si[r], 31);

            float4 o4;
            float Er, Ei;
            // pair 0: steps 0,1
            Er = offR;                  Ei = offI;
            o4.x = g0.x * Er - g0.y * Ei;  o4.y = g0.x * Ei + g0.y * Er;
            Er = offR + PR[r][0];       Ei = offI + PI[r][0];
            o4.z = g0.z * Er - g0.w * Ei;  o4.w = g0.z * Ei + g0.w * Er;
            out4[roff[r] + qb + 0] = o4;
            // pair 1: steps 2,3
            Er = offR + PR[r][1];       Ei = offI + PI[r][1];
            o4.x = g1.x * Er - g1.y * Ei;  o4.y = g1.x * Ei + g1.y * Er;
            Er = offR + PR[r][2];       Ei = offI + PI[r][2];
            o4.z = g1.z * Er - g1.w * Ei;  o4.w = g1.z * Ei + g1.w * Er;
            out4[roff[r] + qb + 1] = o4;
            // pair 2: steps 4,5
            Er = offR + PR[r][3];       Ei = offI + PI[r][3];
            o4.x = g2.x * Er - g2.y * Ei;  o4.y = g2.x * Ei + g2.y * Er;
            Er = offR + PR[r][4];       Ei = offI + PI[r][4];
            o4.z = g2.z * Er - g2.w * Ei;  o4.w = g2.z * Ei + g2.w * Er;
            out4[roff[r] + qb + 2] = o4;
            // pair 3: steps 6,7
            Er = offR + PR[r][5];       Ei = offI + PI[r][5];
            o4.x = g3.x * Er - g3.y * Ei;  o4.y = g3.x * Ei + g3.y * Er;
            Er = offR + PR[r][6];       Ei = offI + PI[r][6];
            o4.z = g3.z * Er - g3.w * Ei;  o4.w = g3.z * Ei + g3.w * Er;
            out4[roff[r] + qb + 3] = o4;
        }
    }
}

// ---------------------------------------------------------------------------
extern "C" void kernel_launch(void* const* d_in, const int* in_sizes, int n_in,
                              void* d_out, int out_size)
{
    const float4* dy4    = (const float4*)d_in[0];
    const float*  coeffs = (const float*)d_in[3];
    float4*       out4   = (float4*)d_out;

    const int B = in_sizes[0] / (T_STEPS * 2);        // 8192
    const int rows_per_block = WARPS_PER_BLOCK * ROWS_PER_WARP;
    const int nblocks = (B + rows_per_block - 1) / rows_per_block;   // 256

    fused_kernel<<<nblocks, 32 * WARPS_PER_BLOCK>>>(dy4, out4, coeffs, B);
}

// round 9
// speedup vs baseline: 1.0695x; 1.0695x over previous
#include <cuda_runtime.h>
#include <cuda_bf16.h>

// Rcell stochastic filter. out[b,t] = c*dt*x_t, x_{t+1} = M_t x_t + u_t dy_t.
// cov is batch-independent and exactly scalar (p_t*I), so M_t = a_t I + dt*k*J
// acts as complex multiplication m_t = alpha_t - i*dt*k on z = x0 + i*x1.
// With g_t = prod_{j<t} m_j:
//   out[b,t] = gs_t * S_t,  S_t = sum_{s<t} h_s * w[b,s]   (complex)
//   gs_t = c*dt*g_t,  h_s = u_s * conj(g_{s+1}) / |g_{s+1}|^2
// Riccati chain (u_t, alpha_t) is coeffs-independent -> compile-time.
// R9: R5/R6 structure (4 rows/warp, 8 interleaved complex chains, per-32-pair
// warp scan) but with 128-thread blocks + launch_bounds(128,5):
// 5 blocks/SM x 4 warps = 20 warps/SM (vs 16) at unchanged per-warp ILP.
// 32-bit row offsets shave pointer registers. 512 blocks = one wave.

#define T_STEPS 2048
#define NPAIR   1024          // T/2: one float4 per 2 steps
#define WARPS_PER_BLOCK 4
#define TPB     (32 * WARPS_PER_BLOCK)   // 128
#define ROWS_PER_WARP   4
#define NCHUNK  (NPAIR / 32)  // 32
#define STEPS_PER_THREAD (T_STEPS / TPB) // 16

// physical constants (f32, matching reference)
#define AAc (-0.15f)                     // -0.5*gamma
#define DDc (1.25f)                      // gamma*(nbar+0.5)+Lambda
#define CCc (1.2649110640673518f)        // sqrt(4*eta*Lambda)
#define DTc (1e-3f)

// ---------------------------------------------------------------------------
// Compile-time Riccati chain: u_t = c*p_t + D, alpha_t = 1 + dt*(a - c*u_t)
// ---------------------------------------------------------------------------
struct PTab { float u[T_STEPS]; float al[T_STEPS]; };

constexpr PTab make_ptab() {
    PTab t{};
    float p = 0.0f;
    for (int i = 0; i < T_STEPS; i++) {
        float uu = CCc * p + DDc;
        t.u[i]  = uu;
        t.al[i] = 1.0f + DTc * (AAc - CCc * uu);
        float dcov = 2.0f * AAc * p + DDc - uu * uu;
        p = p + DTc * dcov;
    }
    return t;
}

__device__ PTab d_ptab = make_ptab();

// ---------------------------------------------------------------------------
__global__ void __launch_bounds__(TPB, 5)
fused_kernel(const float4* __restrict__ dy4, float4* __restrict__ out4,
             const float* __restrict__ coeffs, int B)
{
    __shared__ float4 tabH[NPAIR];   // (h_t0, h_t1) per pair
    __shared__ float4 tabG[NPAIR];   // (gs_t0, gs_t1) per pair
    __shared__ float  wAggR[WARPS_PER_BLOCK], wAggI[WARPS_PER_BLOCK];

    const int tid  = threadIdx.x;
    const int lane = tid & 31;
    const int warp = tid >> 5;

    // ---- phase 1: build tables (128 threads, 16 steps each) ----
    {
        const float beta = DTc * coeffs[0];     // m_t = alpha_t - i*beta

        float pr = 1.0f, pi = 0.0f;
#pragma unroll
        for (int j = 0; j < STEPS_PER_THREAD; j++) {
            float al = d_ptab.al[STEPS_PER_THREAD * tid + j];
            float nr = fmaf(al, pr,  beta * pi);
            float ni = fmaf(al, pi, -beta * pr);
            pr = nr; pi = ni;
        }

        // warp inclusive scan (complex product)
        float sr = pr, si = pi;
#pragma unroll
        for (int o = 1; o < 32; o <<= 1) {
            float tr = __shfl_up_sync(0xFFFFFFFFu, sr, o);
            float ti = __shfl_up_sync(0xFFFFFFFFu, si, o);
            if (lane >= o) {
                float nr = tr * sr - ti * si;
                float ni = tr * si + ti * sr;
                sr = nr; si = ni;
            }
        }
        if (lane == 31) { wAggR[warp] = sr; wAggI[warp] = si; }

        float er = __shfl_up_sync(0xFFFFFFFFu, sr, 1);
        float ei = __shfl_up_sync(0xFFFFFFFFu, si, 1);
        if (lane == 0) { er = 1.0f; ei = 0.0f; }
        __syncthreads();

#pragma unroll
        for (int w = 0; w < WARPS_PER_BLOCK; w++) {
            if (w < warp) {
                float ar = wAggR[w], ai = wAggI[w];
                float nr = er * ar - ei * ai;
                float ni = er * ai + ei * ar;
                er = nr; ei = ni;
            }
        }

        // er,ei = g at step 16*tid; emit 16 entries (8 float4 pairs)
        float gr = er, gi = ei;
        const float K = CCc * DTc;
        float4 H4, G4;
#pragma unroll
        for (int j = 0; j < STEPS_PER_THREAD; j++) {
            int t = STEPS_PER_THREAD * tid + j;
            float al = d_ptab.al[t], u = d_ptab.u[t];
            float gsre = K * gr, gsim = K * gi;          // gs_t = c*dt*g_t
            float g1r = fmaf(al, gr,  beta * gi);        // g_{t+1} = m_t*g_t
            float g1i = fmaf(al, gi, -beta * gr);
            float inv = u / fmaf(g1r, g1r, g1i * g1i);
            float hr =  inv * g1r;                       // h_t
            float hi = -inv * g1i;
            if ((j & 1) == 0) {
                H4.x = hr; H4.y = hi; G4.x = gsre; G4.y = gsim;
            } else {
                H4.z = hr; H4.w = hi; G4.z = gsre; G4.w = gsim;
                tabH[t >> 1] = H4;
                tabG[t >> 1] = G4;
            }
            gr = g1r; gi = g1i;
        }
        __syncthreads();
    }

    // ---- phase 2: each warp scans 4 independent batch rows ----
    const int b0 = (blockIdx.x * WARPS_PER_BLOCK + warp) * ROWS_PER_WARP;

    // one 64-bit base + small 32-bit row offsets (row stride 16KB, 4 rows)
    const float4* dbase = dy4 + (size_t)b0 * NPAIR;
    float4*       obase = out4 + (size_t)b0 * NPAIR;

    float accR[ROWS_PER_WARP], accI[ROWS_PER_WARP];
#pragma unroll
    for (int r = 0; r < ROWS_PER_WARP; r++) { accR[r] = 0.f; accI[r] = 0.f; }

#pragma unroll 2
    for (int c = 0; c < NCHUNK; c++) {
        const int q = c * 32 + lane;
        float4 w[ROWS_PER_WARP];
#pragma unroll
        for (int r = 0; r < ROWS_PER_WARP; r++)
            w[r] = __ldg(dbase + r * NPAIR + q);
        const float4 h = tabH[q];
        const float4 g = tabG[q];

        // per-lane weighted values v = h*w (complex), per row
        float v0r[ROWS_PER_WARP], v0i[ROWS_PER_WARP];
        float sr[ROWS_PER_WARP],  si[ROWS_PER_WARP];
        float Lr[ROWS_PER_WARP],  Li[ROWS_PER_WARP];
#pragma unroll
        for (int r = 0; r < ROWS_PER_WARP; r++) {
            float a0r = h.x * w[r].x - h.y * w[r].y;
            float a0i = h.x * w[r].y + h.y * w[r].x;
            float a1r = h.z * w[r].z - h.w * w[r].w;
            float a1i = h.z * w[r].w + h.w * w[r].z;
            v0r[r] = a0r; v0i[r] = a0i;
            Lr[r] = a0r + a1r; Li[r] = a0i + a1i;
            sr[r] = Lr[r];     si[r] = Li[r];
        }

        // interleaved inclusive warp scans (complex add), 4 rows
#pragma unroll
        for (int o = 1; o < 32; o <<= 1) {
            float tr[ROWS_PER_WARP], ti[ROWS_PER_WARP];
#pragma unroll
            for (int r = 0; r < ROWS_PER_WARP; r++) {
                tr[r] = __shfl_up_sync(0xFFFFFFFFu, sr[r], o);
                ti[r] = __shfl_up_sync(0xFFFFFFFFu, si[r], o);
            }
            if (lane >= o) {
#pragma unroll
                for (int r = 0; r < ROWS_PER_WARP; r++) {
                    sr[r] += tr[r]; si[r] += ti[r];
                }
            }
        }

        // outputs + carry per row
#pragma unroll
        for (int r = 0; r < ROWS_PER_WARP; r++) {
            float Er = accR[r] + (sr[r] - Lr[r]);      // exclusive prefix @ t0
            float Ei = accI[r] + (si[r] - Li[r]);
            float4 o4;
            o4.x = g.x * Er - g.y * Ei;
            o4.y = g.x * Ei + g.y * Er;
            float E1r = Er + v0r[r], E1i = Ei + v0i[r];
            o4.z = g.z * E1r - g.w * E1i;
            o4.w = g.z * E1i + g.w * E1r;
            obase[r * NPAIR + q] = o4;
            accR[r] += __shfl_sync(0xFFFFFFFFu, sr[r], 31);
            accI[r] += __shfl_sync(0xFFFFFFFFu, si[r], 31);
        }
    }
}

// ---------------------------------------------------------------------------
extern "C" void kernel_launch(void* const* d_in, const int* in_sizes, int n_in,
                              void* d_out, int out_size)
{
    const float4* dy4    = (const float4*)d_in[0];
    const float*  coeffs = (const float*)d_in[3];
    float4*       out4   = (float4*)d_out;

    const int B = in_sizes[0] / (T_STEPS * 2);        // 8192
    const int rows_per_block = WARPS_PER_BLOCK * ROWS_PER_WARP;  // 16
    const int nblocks = (B + rows_per_block - 1) / rows_per_block;  // 512

    fused_kernel<<<nblocks, TPB>>>(dy4, out4, coeffs, B);
}